// round 9
// baseline (speedup 1.0000x reference)
#include <cuda_runtime.h>
#include <cuda_fp16.h>
#include <math.h>
#include <stdint.h>

#define B_   16
#define L_   50
#define P_   49
#define T_   20
#define D_   512
#define H_   8
#define DH_  64
#define DFF_ 2048

#define ROWS_IMG (B_*L_*T_)            // 16000
#define ROWS_TIT (B_*L_*P_)            // 39200
#define ROWS_ALL (ROWS_IMG+ROWS_TIT)   // 55200

// ---------------------------------------------------------------------------
// Scratch (device globals)
// ---------------------------------------------------------------------------
__device__ __half g_attn[(size_t)ROWS_ALL * D_];   // fp16 (proj GEMM input)
__device__ float  g_hid [(size_t)ROWS_ALL * D_];   // fp32 (residual)
__device__ __half g_hidh[(size_t)ROWS_ALL * D_];   // fp16 (FFN1 input)
__device__ __half g_ffh [(size_t)ROWS_TIT * DFF_]; // fp16 (FFN2 input)
__device__ float  g_ffo [(size_t)ROWS_TIT * D_];   // fp32
__device__ __half g_wph [D_*D_];                   // fp16 weights
__device__ __half g_w1ih[DFF_*D_];
__device__ __half g_w2ih[D_*DFF_];
__device__ __half g_w1th[DFF_*D_];
__device__ __half g_w2th[D_*DFF_];

// ---------------------------------------------------------------------------
// fp32 -> fp16 conversion (vectorized, grid-stride)
// ---------------------------------------------------------------------------
__global__ void __launch_bounds__(256) to_half_kernel(
    const float* __restrict__ in, __half* __restrict__ out, int n4)
{
    for (int i = blockIdx.x*blockDim.x + threadIdx.x; i < n4; i += gridDim.x*blockDim.x) {
        float4 v = ((const float4*)in)[i];
        __half2 h0 = __floats2half2_rn(v.x, v.y);
        __half2 h1 = __floats2half2_rn(v.z, v.w);
        ((__half2*)out)[2*i]   = h0;
        ((__half2*)out)[2*i+1] = h1;
    }
}

// ---------------------------------------------------------------------------
// Fused attention: one CTA per (b*l, h); outputs fp16
// ---------------------------------------------------------------------------
__global__ void __launch_bounds__(256) attn_kernel(
    const float* __restrict__ img,
    const float* __restrict__ title,
    const int*   __restrict__ mask,
    const float* __restrict__ scale_img,
    const float* __restrict__ scale_title,
    __half*      __restrict__ attn_cat)
{
    const int h   = blockIdx.x & (H_-1);
    const int bl  = blockIdx.x >> 3;
    const int tid = threadIdx.x;

    __shared__ float im[P_][DH_+1];
    __shared__ float ti[T_][DH_+1];
    __shared__ float raw[P_][T_];
    __shared__ float pim[P_][T_];
    __shared__ float pti[T_][P_+3];
    __shared__ float s_si[P_];
    __shared__ float s_st[T_];
    __shared__ int   mk[T_];

    const float* ib = img   + (size_t)bl * (P_*D_) + h*DH_;
    for (int idx = tid; idx < P_*DH_; idx += 256) {
        int p = idx >> 6, d = idx & 63;
        im[p][d] = ib[p*D_ + d];
    }
    const float* tb = title + (size_t)bl * (T_*D_) + h*DH_;
    for (int idx = tid; idx < T_*DH_; idx += 256) {
        int t = idx >> 6, d = idx & 63;
        ti[t][d] = tb[t*D_ + d];
    }
    if (tid < T_) { mk[tid] = mask[bl*T_ + tid]; s_st[tid] = scale_title[h*T_ + tid]; }
    if (tid < P_) s_si[tid] = scale_img[h*P_ + tid];
    __syncthreads();

    for (int idx = tid; idx < P_*T_; idx += 256) {
        int p = idx / T_, t = idx % T_;
        float s = 0.f;
        #pragma unroll 16
        for (int d = 0; d < DH_; d++) s += im[p][d] * ti[t][d];
        raw[p][t] = s * 0.125f;
    }
    __syncthreads();

    if (tid < P_) {
        const int p = tid;
        const float sc = s_si[p];
        float v[T_];
        float mx = -3.4e38f;
        #pragma unroll
        for (int t = 0; t < T_; t++) {
            float x = mk[t] ? raw[p][t]*sc : -1e9f;
            v[t] = x;
            mx = fmaxf(mx, x);
        }
        float s = 0.f;
        #pragma unroll
        for (int t = 0; t < T_; t++) { float e = expf(v[t]-mx); v[t]=e; s+=e; }
        float inv = 1.f/s;
        #pragma unroll
        for (int t = 0; t < T_; t++) pim[p][t] = v[t]*inv;
    }
    if (tid >= 64 && tid < 64+T_) {
        const int t = tid - 64;
        const float sc = s_st[t];
        const bool valid = (mk[t] != 0);
        float mx = -3.4e38f;
        for (int p = 0; p < P_; p++) {
            float x = valid ? raw[p][t]*sc : -1e9f;
            pti[t][p] = x;
            mx = fmaxf(mx, x);
        }
        float s = 0.f;
        for (int p = 0; p < P_; p++) { float e = expf(pti[t][p]-mx); pti[t][p]=e; s+=e; }
        float inv = 1.f/s;
        for (int p = 0; p < P_; p++) pti[t][p] *= inv;
    }
    __syncthreads();

    for (int idx = tid; idx < P_*DH_; idx += 256) {
        int p = idx >> 6, d = idx & 63;
        float s = 0.f;
        #pragma unroll
        for (int t = 0; t < T_; t++) s += pim[p][t]*ti[t][d];
        attn_cat[(size_t)(ROWS_IMG + bl*P_ + p)*D_ + h*DH_ + d] = __float2half_rn(s);
    }
    for (int idx = tid; idx < T_*DH_; idx += 256) {
        int t = idx >> 6, d = idx & 63;
        float s = 0.f;
        #pragma unroll 7
        for (int p = 0; p < P_; p++) s += pti[t][p]*im[p][d];
        attn_cat[(size_t)(bl*T_ + t)*D_ + h*DH_ + d] = __float2half_rn(s);
    }
}

// ---------------------------------------------------------------------------
// fp16 tensor-core GEMM: C = A[M,K]*W[N,K]^T + bias (fp32 accumulate)
// BM=BN=128, BK=64, 256 thr / 8 warps x (64x32 tile), 3-stage cp.async
// (dynamic smem), ONE barrier per k-tile, mma.sync m16n8k16
// MODE: 0 = fp32 out C, 1 = fp16 out Ch, 2 = fp32 C + fp16 Ch
// ---------------------------------------------------------------------------
__device__ __forceinline__ float gelu_t(float x) {
    float x3 = x*x*x;
    return 0.5f*x*(1.f + tanhf(0.7978845608028654f*(x + 0.044715f*x3)));
}

__device__ __forceinline__ void mma_h(float* d, const uint32_t* a, const uint32_t* b) {
    asm volatile(
        "mma.sync.aligned.m16n8k16.row.col.f32.f16.f16.f32 "
        "{%0,%1,%2,%3}, {%4,%5,%6,%7}, {%8,%9}, {%0,%1,%2,%3};"
        : "+f"(d[0]), "+f"(d[1]), "+f"(d[2]), "+f"(d[3])
        : "r"(a[0]), "r"(a[1]), "r"(a[2]), "r"(a[3]), "r"(b[0]), "r"(b[1]));
}

__device__ __forceinline__ void cp16(void* smem_dst, const void* gsrc) {
    uint32_t d = (uint32_t)__cvta_generic_to_shared(smem_dst);
    asm volatile("cp.async.cg.shared.global [%0], [%1], 16;" :: "r"(d), "l"(gsrc));
}

__device__ __forceinline__ void ldsm4(uint32_t* r, uint32_t addr) {
    asm volatile("ldmatrix.sync.aligned.m8n8.x4.shared.b16 {%0,%1,%2,%3}, [%4];"
        : "=r"(r[0]), "=r"(r[1]), "=r"(r[2]), "=r"(r[3]) : "r"(addr));
}

#define HPITCH 72          // halves (144 bytes/row), BK=64 + pad 8
#define STAGES 3
#define STAGE_HALVES (128*HPITCH)               // per operand per stage
#define GSMEM_H (2*STAGES*STAGE_HALVES)          // total halves
#define GSMEM_BYTES (GSMEM_H*2)                  // 110592 bytes

template<int ACT, int MODE>
__global__ void __launch_bounds__(256, 2) gemm_h(
    const __half* __restrict__ A, const __half* __restrict__ W,
    const float* __restrict__ bias, float* __restrict__ C,
    __half* __restrict__ Ch, int M, int N, int K)
{
    extern __shared__ __half dynsm[];
    // layout: A stages [0..2], then W stages [0..2]
    __half* Asm[STAGES];
    __half* Wsm[STAGES];
    #pragma unroll
    for (int s = 0; s < STAGES; s++) {
        Asm[s] = dynsm + (size_t)s * STAGE_HALVES;
        Wsm[s] = dynsm + (size_t)(STAGES + s) * STAGE_HALVES;
    }

    const int tid  = threadIdx.x;
    const int lane = tid & 31;
    const int warp = tid >> 5;
    const int wm   = warp >> 2;     // 0..1
    const int wn   = warp & 3;      // 0..3

    const int bn = blockIdx.x * 128;
    const int bm = blockIdx.y * 128;

    // staging: thread -> row tid>>1, halves (tid&1)*32 .. +32  (4x cp16)
    const int srow = tid >> 1;
    const int sc0  = (tid & 1) * 32;
    const int  arow = bm + srow;
    const bool aok  = arow < M;
    const __half* Ap = A + (size_t)arow * K + sc0;
    const __half* Wp = W + (size_t)(bn + srow) * K + sc0;

    if (!aok) {
        #pragma unroll
        for (int s = 0; s < STAGES; s++)
            #pragma unroll
            for (int j = 0; j < 32; j++)
                Asm[s][srow*HPITCH + sc0 + j] = __float2half_rn(0.f);
    }

    float acc[4][4][4];
    #pragma unroll
    for (int mt = 0; mt < 4; mt++)
        #pragma unroll
        for (int nt = 0; nt < 4; nt++)
            #pragma unroll
            for (int r = 0; r < 4; r++) acc[mt][nt][r] = 0.f;

    const int KT = K >> 6;

    // prologue: stages 0..1
    #pragma unroll
    for (int s = 0; s < 2; s++) {
        const int ko = s << 6;
        if (aok) {
            #pragma unroll
            for (int j = 0; j < 4; j++)
                cp16(&Asm[s][srow*HPITCH + sc0 + j*8], Ap + ko + j*8);
        }
        #pragma unroll
        for (int j = 0; j < 4; j++)
            cp16(&Wsm[s][srow*HPITCH + sc0 + j*8], Wp + ko + j*8);
        asm volatile("cp.async.commit_group;");
    }

    // ldmatrix lane->address maps (round-7-verified fragment layouts)
    const int a_row  = wm*64 + (lane & 15);
    const int a_colh = ((lane >> 4) & 1) * 8;
    const int b_row  = wn*32 + (lane & 7) + ((lane & 16) >> 1);
    const int b_colh = ((lane >> 3) & 1) * 8;
    uint32_t a_base[STAGES], b_base[STAGES];
    #pragma unroll
    for (int s = 0; s < STAGES; s++) {
        a_base[s] = (uint32_t)__cvta_generic_to_shared(&Asm[s][a_row*HPITCH + a_colh]);
        b_base[s] = (uint32_t)__cvta_generic_to_shared(&Wsm[s][b_row*HPITCH + b_colh]);
    }

    for (int kt = 0; kt < KT; kt++) {
        const int cur = kt % STAGES;
        asm volatile("cp.async.wait_group 1;");
        __syncthreads();   // single barrier per iter: protects stage (kt-1)%3 reuse below

        if (kt + 2 < KT) {
            const int nb = (kt + 2) % STAGES;   // == (kt-1)%3, safe after barrier
            const int ko = (kt + 2) << 6;
            if (aok) {
                #pragma unroll
                for (int j = 0; j < 4; j++)
                    cp16(&Asm[nb][srow*HPITCH + sc0 + j*8], Ap + ko + j*8);
            }
            #pragma unroll
            for (int j = 0; j < 4; j++)
                cp16(&Wsm[nb][srow*HPITCH + sc0 + j*8], Wp + ko + j*8);
            asm volatile("cp.async.commit_group;");
        }

        #pragma unroll
        for (int kh = 0; kh < 4; kh++) {       // four k16 slices of BK=64
            uint32_t af[4][4], bf[2][4];
            #pragma unroll
            for (int mt = 0; mt < 4; mt++)
                ldsm4(af[mt], a_base[cur] + (uint32_t)((kh*16 + mt*16*HPITCH) * 2));
            #pragma unroll
            for (int pr = 0; pr < 2; pr++)
                ldsm4(bf[pr], b_base[cur] + (uint32_t)((kh*16 + pr*16*HPITCH) * 2));
            #pragma unroll
            for (int mt = 0; mt < 4; mt++)
                #pragma unroll
                for (int nt = 0; nt < 4; nt++)
                    mma_h(acc[mt][nt], af[mt], &bf[nt>>1][(nt&1)*2]);
        }
    }

    // epilogue (acc layout: lane>>2 -> row, rows +0/+8; cols 2*(lane&3)+{0,1})
    const int cn = bn + wn*32;
    float bv[4][2];
    #pragma unroll
    for (int nt = 0; nt < 4; nt++) {
        int c = cn + nt*8 + 2*(lane & 3);
        bv[nt][0] = bias[c];
        bv[nt][1] = bias[c+1];
    }
    #pragma unroll
    for (int mt = 0; mt < 4; mt++) {
        const int r0 = bm + wm*64 + mt*16 + (lane >> 2);
        #pragma unroll
        for (int half = 0; half < 2; half++) {
            const int r = r0 + half*8;
            if (r < M) {
                #pragma unroll
                for (int nt = 0; nt < 4; nt++) {
                    float x0 = acc[mt][nt][half*2+0] + bv[nt][0];
                    float x1 = acc[mt][nt][half*2+1] + bv[nt][1];
                    if (ACT) { x0 = gelu_t(x0); x1 = gelu_t(x1); }
                    const size_t off = (size_t)r*N + cn + nt*8 + 2*(lane & 3);
                    if (MODE == 0) {
                        *(float2*)&C[off] = make_float2(x0, x1);
                    } else if (MODE == 1) {
                        *(__half2*)&Ch[off] = __floats2half2_rn(x0, x1);
                    } else {
                        *(float2*)&C[off]   = make_float2(x0, x1);
                        *(__half2*)&Ch[off] = __floats2half2_rn(x0, x1);
                    }
                }
            }
        }
    }
}

// ---------------------------------------------------------------------------
// out[row] = hid[row] + a*(x-mean)/(std(ddof=1)+eps) + b
// ---------------------------------------------------------------------------
__global__ void __launch_bounds__(128) ln_res_kernel(
    const float* __restrict__ hid, const float* __restrict__ ffn,
    const float* __restrict__ ga,  const float* __restrict__ gb,
    float* __restrict__ out)
{
    const int row = blockIdx.x;
    const int tid = threadIdx.x;
    float4 xv = ((const float4*)(ffn + (size_t)row*D_))[tid];
    float s = xv.x + xv.y + xv.z + xv.w;
    float q = xv.x*xv.x + xv.y*xv.y + xv.z*xv.z + xv.w*xv.w;
    #pragma unroll
    for (int o = 16; o > 0; o >>= 1) {
        s += __shfl_xor_sync(0xffffffffu, s, o);
        q += __shfl_xor_sync(0xffffffffu, q, o);
    }
    __shared__ float ss[4], sq[4];
    if ((tid & 31) == 0) { ss[tid>>5] = s; sq[tid>>5] = q; }
    __syncthreads();
    float S = ss[0]+ss[1]+ss[2]+ss[3];
    float Q = sq[0]+sq[1]+sq[2]+sq[3];
    float mean = S * (1.f/D_);
    float var  = (Q - (float)D_*mean*mean) * (1.f/(D_-1));
    var = fmaxf(var, 0.f);
    float inv = 1.f / (sqrtf(var) + 1e-6f);

    float4 hv = ((const float4*)(hid + (size_t)row*D_))[tid];
    float4 av = ((const float4*)ga)[tid];
    float4 bv = ((const float4*)gb)[tid];
    float4 o4;
    o4.x = hv.x + av.x*(xv.x-mean)*inv + bv.x;
    o4.y = hv.y + av.y*(xv.y-mean)*inv + bv.y;
    o4.z = hv.z + av.z*(xv.z-mean)*inv + bv.z;
    o4.w = hv.w + av.w*(xv.w-mean)*inv + bv.w;
    ((float4*)(out + (size_t)row*D_))[tid] = o4;
}

// ---------------------------------------------------------------------------
extern "C" void kernel_launch(void* const* d_in, const int* in_sizes, int n_in,
                              void* d_out, int out_size)
{
    const float* img    = (const float*)d_in[0];
    const float* title  = (const float*)d_in[1];
    const int*   mask   = (const int*)  d_in[2];
    const float* s_img  = (const float*)d_in[3];
    const float* s_tit  = (const float*)d_in[4];
    const float* w_proj = (const float*)d_in[5];
    const float* b_proj = (const float*)d_in[6];
    const float* w1i    = (const float*)d_in[7];
    const float* b1i    = (const float*)d_in[8];
    const float* w2i    = (const float*)d_in[9];
    const float* b2i    = (const float*)d_in[10];
    const float* w1t    = (const float*)d_in[11];
    const float* b1t    = (const float*)d_in[12];
    const float* w2t    = (const float*)d_in[13];
    const float* b2t    = (const float*)d_in[14];
    const float* lai    = (const float*)d_in[15];
    const float* lbi    = (const float*)d_in[16];
    const float* lat    = (const float*)d_in[17];
    const float* lbt    = (const float*)d_in[18];
    float* out = (float*)d_out;

    __half *attn, *hidh, *ffh, *wph, *w1ih, *w2ih, *w1th, *w2th;
    float *hid, *ffo;
    cudaGetSymbolAddress((void**)&attn, g_attn);
    cudaGetSymbolAddress((void**)&hid,  g_hid);
    cudaGetSymbolAddress((void**)&hidh, g_hidh);
    cudaGetSymbolAddress((void**)&ffh,  g_ffh);
    cudaGetSymbolAddress((void**)&ffo,  g_ffo);
    cudaGetSymbolAddress((void**)&wph,  g_wph);
    cudaGetSymbolAddress((void**)&w1ih, g_w1ih);
    cudaGetSymbolAddress((void**)&w2ih, g_w2ih);
    cudaGetSymbolAddress((void**)&w1th, g_w1th);
    cudaGetSymbolAddress((void**)&w2th, g_w2th);

    cudaFuncSetAttribute(gemm_h<0,2>, cudaFuncAttributeMaxDynamicSharedMemorySize, GSMEM_BYTES);
    cudaFuncSetAttribute(gemm_h<1,1>, cudaFuncAttributeMaxDynamicSharedMemorySize, GSMEM_BYTES);
    cudaFuncSetAttribute(gemm_h<0,0>, cudaFuncAttributeMaxDynamicSharedMemorySize, GSMEM_BYTES);

    // weight fp16 conversion (~9MB writes)
    to_half_kernel<<<256, 256>>>(w_proj, wph, D_*D_/4);
    to_half_kernel<<<512, 256>>>(w1i, w1ih, DFF_*D_/4);
    to_half_kernel<<<512, 256>>>(w2i, w2ih, D_*DFF_/4);
    to_half_kernel<<<512, 256>>>(w1t, w1th, DFF_*D_/4);
    to_half_kernel<<<512, 256>>>(w2t, w2th, D_*DFF_/4);

    attn_kernel<<<B_*L_*H_, 256>>>(img, title, mask, s_img, s_tit, attn);

    dim3 gP(D_/128, (ROWS_ALL+127)/128);
    gemm_h<0,2><<<gP, 256, GSMEM_BYTES>>>(attn, wph, b_proj, hid, hidh, ROWS_ALL, D_, D_);

    dim3 g1i(DFF_/128, (ROWS_IMG+127)/128);
    gemm_h<1,1><<<g1i, 256, GSMEM_BYTES>>>(hidh, w1ih, b1i, (float*)0, ffh, ROWS_IMG, DFF_, D_);
    dim3 g2i(D_/128, (ROWS_IMG+127)/128);
    gemm_h<0,0><<<g2i, 256, GSMEM_BYTES>>>(ffh, w2ih, b2i, ffo, (__half*)0, ROWS_IMG, D_, DFF_);
    ln_res_kernel<<<ROWS_IMG, 128>>>(hid, ffo, lai, lbi, out);

    const __half* hidhT = hidh + (size_t)ROWS_IMG*D_;
    dim3 g1t(DFF_/128, (ROWS_TIT+127)/128);
    gemm_h<1,1><<<g1t, 256, GSMEM_BYTES>>>(hidhT, w1th, b1t, (float*)0, ffh, ROWS_TIT, DFF_, D_);
    dim3 g2t(D_/128, (ROWS_TIT+127)/128);
    gemm_h<0,0><<<g2t, 256, GSMEM_BYTES>>>(ffh, w2th, b2t, ffo, (__half*)0, ROWS_TIT, D_, DFF_);
    ln_res_kernel<<<ROWS_TIT, 128>>>(hid + (size_t)ROWS_IMG*D_, ffo, lat, lbt,
                                     out + (size_t)ROWS_IMG*D_);
}

// round 10
// speedup vs baseline: 1.0748x; 1.0748x over previous
#include <cuda_runtime.h>
#include <cuda_fp16.h>
#include <math.h>
#include <stdint.h>

#define B_   16
#define L_   50
#define P_   49
#define T_   20
#define D_   512
#define H_   8
#define DH_  64
#define DFF_ 2048

#define ROWS_IMG (B_*L_*T_)            // 16000
#define ROWS_TIT (B_*L_*P_)            // 39200
#define ROWS_ALL (ROWS_IMG+ROWS_TIT)   // 55200

// ---------------------------------------------------------------------------
// Scratch (device globals)
// ---------------------------------------------------------------------------
__device__ __half g_attn[(size_t)ROWS_ALL * D_];   // fp16 (proj GEMM input)
__device__ float  g_hid [(size_t)ROWS_ALL * D_];   // fp32 (residual)
__device__ __half g_hidh[(size_t)ROWS_ALL * D_];   // fp16 (FFN1 input)
__device__ __half g_ffh [(size_t)ROWS_TIT * DFF_]; // fp16 (FFN2 input)
__device__ float  g_ffo [(size_t)ROWS_TIT * D_];   // fp32
__device__ __half g_wph [D_*D_];                   // fp16 weights
__device__ __half g_w1ih[DFF_*D_];
__device__ __half g_w2ih[D_*DFF_];
__device__ __half g_w1th[DFF_*D_];
__device__ __half g_w2th[D_*DFF_];

// ---------------------------------------------------------------------------
// fp32 -> fp16 conversion (vectorized, grid-stride)
// ---------------------------------------------------------------------------
__global__ void __launch_bounds__(256) to_half_kernel(
    const float* __restrict__ in, __half* __restrict__ out, int n4)
{
    for (int i = blockIdx.x*blockDim.x + threadIdx.x; i < n4; i += gridDim.x*blockDim.x) {
        float4 v = ((const float4*)in)[i];
        __half2 h0 = __floats2half2_rn(v.x, v.y);
        __half2 h1 = __floats2half2_rn(v.z, v.w);
        ((__half2*)out)[2*i]   = h0;
        ((__half2*)out)[2*i+1] = h1;
    }
}

// ---------------------------------------------------------------------------
// Fused attention: one CTA per (b*l, h); outputs fp16
// ---------------------------------------------------------------------------
__global__ void __launch_bounds__(256) attn_kernel(
    const float* __restrict__ img,
    const float* __restrict__ title,
    const int*   __restrict__ mask,
    const float* __restrict__ scale_img,
    const float* __restrict__ scale_title,
    __half*      __restrict__ attn_cat)
{
    const int h   = blockIdx.x & (H_-1);
    const int bl  = blockIdx.x >> 3;
    const int tid = threadIdx.x;

    __shared__ float im[P_][DH_+1];
    __shared__ float ti[T_][DH_+1];
    __shared__ float raw[P_][T_];
    __shared__ float pim[P_][T_];
    __shared__ float pti[T_][P_+3];
    __shared__ float s_si[P_];
    __shared__ float s_st[T_];
    __shared__ int   mk[T_];

    const float* ib = img   + (size_t)bl * (P_*D_) + h*DH_;
    for (int idx = tid; idx < P_*DH_; idx += 256) {
        int p = idx >> 6, d = idx & 63;
        im[p][d] = ib[p*D_ + d];
    }
    const float* tb = title + (size_t)bl * (T_*D_) + h*DH_;
    for (int idx = tid; idx < T_*DH_; idx += 256) {
        int t = idx >> 6, d = idx & 63;
        ti[t][d] = tb[t*D_ + d];
    }
    if (tid < T_) { mk[tid] = mask[bl*T_ + tid]; s_st[tid] = scale_title[h*T_ + tid]; }
    if (tid < P_) s_si[tid] = scale_img[h*P_ + tid];
    __syncthreads();

    for (int idx = tid; idx < P_*T_; idx += 256) {
        int p = idx / T_, t = idx % T_;
        float s = 0.f;
        #pragma unroll 16
        for (int d = 0; d < DH_; d++) s += im[p][d] * ti[t][d];
        raw[p][t] = s * 0.125f;
    }
    __syncthreads();

    if (tid < P_) {
        const int p = tid;
        const float sc = s_si[p];
        float v[T_];
        float mx = -3.4e38f;
        #pragma unroll
        for (int t = 0; t < T_; t++) {
            float x = mk[t] ? raw[p][t]*sc : -1e9f;
            v[t] = x;
            mx = fmaxf(mx, x);
        }
        float s = 0.f;
        #pragma unroll
        for (int t = 0; t < T_; t++) { float e = expf(v[t]-mx); v[t]=e; s+=e; }
        float inv = 1.f/s;
        #pragma unroll
        for (int t = 0; t < T_; t++) pim[p][t] = v[t]*inv;
    }
    if (tid >= 64 && tid < 64+T_) {
        const int t = tid - 64;
        const float sc = s_st[t];
        const bool valid = (mk[t] != 0);
        float mx = -3.4e38f;
        for (int p = 0; p < P_; p++) {
            float x = valid ? raw[p][t]*sc : -1e9f;
            pti[t][p] = x;
            mx = fmaxf(mx, x);
        }
        float s = 0.f;
        for (int p = 0; p < P_; p++) { float e = expf(pti[t][p]-mx); pti[t][p]=e; s+=e; }
        float inv = 1.f/s;
        for (int p = 0; p < P_; p++) pti[t][p] *= inv;
    }
    __syncthreads();

    for (int idx = tid; idx < P_*DH_; idx += 256) {
        int p = idx >> 6, d = idx & 63;
        float s = 0.f;
        #pragma unroll
        for (int t = 0; t < T_; t++) s += pim[p][t]*ti[t][d];
        attn_cat[(size_t)(ROWS_IMG + bl*P_ + p)*D_ + h*DH_ + d] = __float2half_rn(s);
    }
    for (int idx = tid; idx < T_*DH_; idx += 256) {
        int t = idx >> 6, d = idx & 63;
        float s = 0.f;
        #pragma unroll 7
        for (int p = 0; p < P_; p++) s += pti[t][p]*im[p][d];
        attn_cat[(size_t)(bl*T_ + t)*D_ + h*DH_ + d] = __float2half_rn(s);
    }
}

// ---------------------------------------------------------------------------
// fp16 tensor-core GEMM: C = A[M,K]*W[N,K]^T + bias (fp32 accumulate)
// BM=BN=128, BK=32, 256 thr / 8 warps x (64x32 tile), 3-stage cp.async
// (static smem, 2 CTA/SM), ONE barrier per k-tile, mma.sync m16n8k16
// MODE: 0 = fp32 out C, 1 = fp16 out Ch, 2 = fp32 C + fp16 Ch
// ---------------------------------------------------------------------------
__device__ __forceinline__ float gelu_t(float x) {
    float x3 = x*x*x;
    return 0.5f*x*(1.f + tanhf(0.7978845608028654f*(x + 0.044715f*x3)));
}

__device__ __forceinline__ void mma_h(float* d, const uint32_t* a, const uint32_t* b) {
    asm volatile(
        "mma.sync.aligned.m16n8k16.row.col.f32.f16.f16.f32 "
        "{%0,%1,%2,%3}, {%4,%5,%6,%7}, {%8,%9}, {%0,%1,%2,%3};"
        : "+f"(d[0]), "+f"(d[1]), "+f"(d[2]), "+f"(d[3])
        : "r"(a[0]), "r"(a[1]), "r"(a[2]), "r"(a[3]), "r"(b[0]), "r"(b[1]));
}

__device__ __forceinline__ void cp16(void* smem_dst, const void* gsrc) {
    uint32_t d = (uint32_t)__cvta_generic_to_shared(smem_dst);
    asm volatile("cp.async.cg.shared.global [%0], [%1], 16;" :: "r"(d), "l"(gsrc));
}

__device__ __forceinline__ void ldsm4(uint32_t* r, uint32_t addr) {
    asm volatile("ldmatrix.sync.aligned.m8n8.x4.shared.b16 {%0,%1,%2,%3}, [%4];"
        : "=r"(r[0]), "=r"(r[1]), "=r"(r[2]), "=r"(r[3]) : "r"(addr));
}

#define HPITCH 40          // halves (80 bytes/row)
#define STAGES 3

template<int ACT, int MODE>
__global__ void __launch_bounds__(256, 2) gemm_h(
    const __half* __restrict__ A, const __half* __restrict__ W,
    const float* __restrict__ bias, float* __restrict__ C,
    __half* __restrict__ Ch, int M, int N, int K)
{
    __shared__ __half As[STAGES][128][HPITCH];
    __shared__ __half Ws[STAGES][128][HPITCH];

    const int tid  = threadIdx.x;
    const int lane = tid & 31;
    const int warp = tid >> 5;
    const int wm   = warp >> 2;     // 0..1
    const int wn   = warp & 3;      // 0..3

    const int bn = blockIdx.x * 128;
    const int bm = blockIdx.y * 128;

    // staging: thread -> row tid>>1, halves (tid&1)*16 .. +16  (2x cp16)
    const int srow = tid >> 1;
    const int scol = (tid & 1) * 16;
    const int  arow = bm + srow;
    const bool aok  = arow < M;
    const __half* Ap = A + (size_t)arow * K + scol;
    const __half* Wp = W + (size_t)(bn + srow) * K + scol;

    if (!aok) {
        #pragma unroll
        for (int s = 0; s < STAGES; s++)
            #pragma unroll
            for (int j = 0; j < 16; j++)
                As[s][srow][scol + j] = __float2half_rn(0.f);
    }

    float acc[4][4][4];
    #pragma unroll
    for (int mt = 0; mt < 4; mt++)
        #pragma unroll
        for (int nt = 0; nt < 4; nt++)
            #pragma unroll
            for (int r = 0; r < 4; r++) acc[mt][nt][r] = 0.f;

    const int KT = K >> 5;

    // prologue: stages 0..1
    #pragma unroll
    for (int s = 0; s < 2; s++) {
        const int ko = s << 5;
        if (aok) { cp16(&As[s][srow][scol], Ap + ko); cp16(&As[s][srow][scol+8], Ap + ko + 8); }
        cp16(&Ws[s][srow][scol], Wp + ko); cp16(&Ws[s][srow][scol+8], Wp + ko + 8);
        asm volatile("cp.async.commit_group;");
    }

    // ldmatrix lane->address maps (round-7-verified fragment layouts)
    const int a_row  = wm*64 + (lane & 15);
    const int a_colh = ((lane >> 4) & 1) * 8;
    const int b_row  = wn*32 + (lane & 7) + ((lane & 16) >> 1);
    const int b_colh = ((lane >> 3) & 1) * 8;
    uint32_t a_base[STAGES], b_base[STAGES];
    #pragma unroll
    for (int s = 0; s < STAGES; s++) {
        a_base[s] = (uint32_t)__cvta_generic_to_shared(&As[s][a_row][a_colh]);
        b_base[s] = (uint32_t)__cvta_generic_to_shared(&Ws[s][b_row][b_colh]);
    }

    for (int kt = 0; kt < KT; kt++) {
        const int cur = kt % STAGES;
        asm volatile("cp.async.wait_group 1;");
        __syncthreads();
        // Single barrier per iteration. The cp.async below targets stage
        // (kt+2)%3 == (kt-1)%3, whose ldsm reads (iter kt-1) completed before
        // every thread arrived at the barrier above. The stage being read now
        // (cur) is only overwritten by iter kt+1's cp, issued after iter
        // kt+1's barrier, i.e. after this iteration's ldsm reads finish.

        if (kt + 2 < KT) {
            const int nb = (kt + 2) % STAGES;
            const int ko = (kt + 2) << 5;
            if (aok) { cp16(&As[nb][srow][scol], Ap + ko); cp16(&As[nb][srow][scol+8], Ap + ko + 8); }
            cp16(&Ws[nb][srow][scol], Wp + ko); cp16(&Ws[nb][srow][scol+8], Wp + ko + 8);
            asm volatile("cp.async.commit_group;");
        }

        #pragma unroll
        for (int kh = 0; kh < 2; kh++) {            // two k16 halves of BK=32
            uint32_t af[4][4], bf[2][4];
            #pragma unroll
            for (int mt = 0; mt < 4; mt++)
                ldsm4(af[mt], a_base[cur] + (uint32_t)((kh*16 + mt*16*HPITCH) * 2));
            #pragma unroll
            for (int pr = 0; pr < 2; pr++)
                ldsm4(bf[pr], b_base[cur] + (uint32_t)((kh*16 + pr*16*HPITCH) * 2));
            #pragma unroll
            for (int mt = 0; mt < 4; mt++)
                #pragma unroll
                for (int nt = 0; nt < 4; nt++)
                    mma_h(acc[mt][nt], af[mt], &bf[nt>>1][(nt&1)*2]);
        }
    }

    // epilogue (acc layout: lane>>2 -> row, rows +0/+8; cols 2*(lane&3)+{0,1})
    const int cn = bn + wn*32;
    float bv[4][2];
    #pragma unroll
    for (int nt = 0; nt < 4; nt++) {
        int c = cn + nt*8 + 2*(lane & 3);
        bv[nt][0] = bias[c];
        bv[nt][1] = bias[c+1];
    }
    #pragma unroll
    for (int mt = 0; mt < 4; mt++) {
        const int r0 = bm + wm*64 + mt*16 + (lane >> 2);
        #pragma unroll
        for (int half = 0; half < 2; half++) {
            const int r = r0 + half*8;
            if (r < M) {
                #pragma unroll
                for (int nt = 0; nt < 4; nt++) {
                    float x0 = acc[mt][nt][half*2+0] + bv[nt][0];
                    float x1 = acc[mt][nt][half*2+1] + bv[nt][1];
                    if (ACT) { x0 = gelu_t(x0); x1 = gelu_t(x1); }
                    const size_t off = (size_t)r*N + cn + nt*8 + 2*(lane & 3);
                    if (MODE == 0) {
                        *(float2*)&C[off] = make_float2(x0, x1);
                    } else if (MODE == 1) {
                        *(__half2*)&Ch[off] = __floats2half2_rn(x0, x1);
                    } else {
                        *(float2*)&C[off]   = make_float2(x0, x1);
                        *(__half2*)&Ch[off] = __floats2half2_rn(x0, x1);
                    }
                }
            }
        }
    }
}

// ---------------------------------------------------------------------------
// out[row] = hid[row] + a*(x-mean)/(std(ddof=1)+eps) + b
// ---------------------------------------------------------------------------
__global__ void __launch_bounds__(128) ln_res_kernel(
    const float* __restrict__ hid, const float* __restrict__ ffn,
    const float* __restrict__ ga,  const float* __restrict__ gb,
    float* __restrict__ out)
{
    const int row = blockIdx.x;
    const int tid = threadIdx.x;
    float4 xv = ((const float4*)(ffn + (size_t)row*D_))[tid];
    float s = xv.x + xv.y + xv.z + xv.w;
    float q = xv.x*xv.x + xv.y*xv.y + xv.z*xv.z + xv.w*xv.w;
    #pragma unroll
    for (int o = 16; o > 0; o >>= 1) {
        s += __shfl_xor_sync(0xffffffffu, s, o);
        q += __shfl_xor_sync(0xffffffffu, q, o);
    }
    __shared__ float ss[4], sq[4];
    if ((tid & 31) == 0) { ss[tid>>5] = s; sq[tid>>5] = q; }
    __syncthreads();
    float S = ss[0]+ss[1]+ss[2]+ss[3];
    float Q = sq[0]+sq[1]+sq[2]+sq[3];
    float mean = S * (1.f/D_);
    float var  = (Q - (float)D_*mean*mean) * (1.f/(D_-1));
    var = fmaxf(var, 0.f);
    float inv = 1.f / (sqrtf(var) + 1e-6f);

    float4 hv = ((const float4*)(hid + (size_t)row*D_))[tid];
    float4 av = ((const float4*)ga)[tid];
    float4 bv = ((const float4*)gb)[tid];
    float4 o4;
    o4.x = hv.x + av.x*(xv.x-mean)*inv + bv.x;
    o4.y = hv.y + av.y*(xv.y-mean)*inv + bv.y;
    o4.z = hv.z + av.z*(xv.z-mean)*inv + bv.z;
    o4.w = hv.w + av.w*(xv.w-mean)*inv + bv.w;
    ((float4*)(out + (size_t)row*D_))[tid] = o4;
}

// ---------------------------------------------------------------------------
extern "C" void kernel_launch(void* const* d_in, const int* in_sizes, int n_in,
                              void* d_out, int out_size)
{
    const float* img    = (const float*)d_in[0];
    const float* title  = (const float*)d_in[1];
    const int*   mask   = (const int*)  d_in[2];
    const float* s_img  = (const float*)d_in[3];
    const float* s_tit  = (const float*)d_in[4];
    const float* w_proj = (const float*)d_in[5];
    const float* b_proj = (const float*)d_in[6];
    const float* w1i    = (const float*)d_in[7];
    const float* b1i    = (const float*)d_in[8];
    const float* w2i    = (const float*)d_in[9];
    const float* b2i    = (const float*)d_in[10];
    const float* w1t    = (const float*)d_in[11];
    const float* b1t    = (const float*)d_in[12];
    const float* w2t    = (const float*)d_in[13];
    const float* b2t    = (const float*)d_in[14];
    const float* lai    = (const float*)d_in[15];
    const float* lbi    = (const float*)d_in[16];
    const float* lat    = (const float*)d_in[17];
    const float* lbt    = (const float*)d_in[18];
    float* out = (float*)d_out;

    __half *attn, *hidh, *ffh, *wph, *w1ih, *w2ih, *w1th, *w2th;
    float *hid, *ffo;
    cudaGetSymbolAddress((void**)&attn, g_attn);
    cudaGetSymbolAddress((void**)&hid,  g_hid);
    cudaGetSymbolAddress((void**)&hidh, g_hidh);
    cudaGetSymbolAddress((void**)&ffh,  g_ffh);
    cudaGetSymbolAddress((void**)&ffo,  g_ffo);
    cudaGetSymbolAddress((void**)&wph,  g_wph);
    cudaGetSymbolAddress((void**)&w1ih, g_w1ih);
    cudaGetSymbolAddress((void**)&w2ih, g_w2ih);
    cudaGetSymbolAddress((void**)&w1th, g_w1th);
    cudaGetSymbolAddress((void**)&w2th, g_w2th);

    // weight fp16 conversion (~9MB writes)
    to_half_kernel<<<256, 256>>>(w_proj, wph, D_*D_/4);
    to_half_kernel<<<512, 256>>>(w1i, w1ih, DFF_*D_/4);
    to_half_kernel<<<512, 256>>>(w2i, w2ih, D_*DFF_/4);
    to_half_kernel<<<512, 256>>>(w1t, w1th, DFF_*D_/4);
    to_half_kernel<<<512, 256>>>(w2t, w2th, D_*DFF_/4);

    attn_kernel<<<B_*L_*H_, 256>>>(img, title, mask, s_img, s_tit, attn);

    dim3 gP(D_/128, (ROWS_ALL+127)/128);
    gemm_h<0,2><<<gP, 256>>>(attn, wph, b_proj, hid, hidh, ROWS_ALL, D_, D_);

    dim3 g1i(DFF_/128, (ROWS_IMG+127)/128);
    gemm_h<1,1><<<g1i, 256>>>(hidh, w1ih, b1i, (float*)0, ffh, ROWS_IMG, DFF_, D_);
    dim3 g2i(D_/128, (ROWS_IMG+127)/128);
    gemm_h<0,0><<<g2i, 256>>>(ffh, w2ih, b2i, ffo, (__half*)0, ROWS_IMG, D_, DFF_);
    ln_res_kernel<<<ROWS_IMG, 128>>>(hid, ffo, lai, lbi, out);

    const __half* hidhT = hidh + (size_t)ROWS_IMG*D_;
    dim3 g1t(DFF_/128, (ROWS_TIT+127)/128);
    gemm_h<1,1><<<g1t, 256>>>(hidhT, w1th, b1t, (float*)0, ffh, ROWS_TIT, DFF_, D_);
    dim3 g2t(D_/128, (ROWS_TIT+127)/128);
    gemm_h<0,0><<<g2t, 256>>>(ffh, w2th, b2t, ffo, (__half*)0, ROWS_TIT, D_, DFF_);
    ln_res_kernel<<<ROWS_TIT, 128>>>(hid + (size_t)ROWS_IMG*D_, ffo, lat, lbt,
                                     out + (size_t)ROWS_IMG*D_);
}

// round 13
// speedup vs baseline: 1.1240x; 1.0458x over previous
#include <cuda_runtime.h>
#include <cuda_fp16.h>
#include <math.h>
#include <stdint.h>

#define B_   16
#define L_   50
#define P_   49
#define T_   20
#define D_   512
#define H_   8
#define DH_  64
#define DFF_ 2048

#define ROWS_IMG (B_*L_*T_)            // 16000  (= 125 * 128, tile-aligned!)
#define ROWS_TIT (B_*L_*P_)            // 39200
#define ROWS_ALL (ROWS_IMG+ROWS_TIT)   // 55200

// ---------------------------------------------------------------------------
// Scratch (device globals)
// ---------------------------------------------------------------------------
__device__ __half g_attn[(size_t)ROWS_ALL * D_];   // fp16 (proj GEMM input)
__device__ float  g_hid [(size_t)ROWS_ALL * D_];   // fp32 (residual)
__device__ __half g_hidh[(size_t)ROWS_ALL * D_];   // fp16 (FFN1 input)
__device__ __half g_ffh [(size_t)ROWS_ALL * DFF_]; // merged gelu out (fp16)
__device__ float  g_ffo [(size_t)ROWS_ALL * D_];   // merged ffn out (fp32)
__device__ __half g_wph [D_*D_];                   // fp16 weights
__device__ __half g_w1ih[DFF_*D_];
__device__ __half g_w2ih[D_*DFF_];
__device__ __half g_w1th[DFF_*D_];
__device__ __half g_w2th[D_*DFF_];

// ---------------------------------------------------------------------------
// Convert all 5 weight matrices fp32 -> fp16 in ONE launch (grid-stride)
// ---------------------------------------------------------------------------
__global__ void __launch_bounds__(256) to_half_all(
    const float* __restrict__ w0, const float* __restrict__ w1,
    const float* __restrict__ w2, const float* __restrict__ w3,
    const float* __restrict__ w4,
    __half* __restrict__ o0, __half* __restrict__ o1,
    __half* __restrict__ o2, __half* __restrict__ o3,
    __half* __restrict__ o4)
{
    const int N0 = D_*D_/4;            // 65536 float4
    const int N1 = DFF_*D_/4;          // 262144 float4
    const int NT = N0 + 4*N1;
    for (int i = blockIdx.x*blockDim.x + threadIdx.x; i < NT; i += gridDim.x*blockDim.x) {
        const float* in; __half* out; int j;
        if (i < N0) { in = w0; out = o0; j = i; }
        else {
            int k = (i - N0) / N1, r = (i - N0) % N1;
            in  = (k == 0) ? w1 : (k == 1) ? w2 : (k == 2) ? w3 : w4;
            out = (k == 0) ? o1 : (k == 1) ? o2 : (k == 2) ? o3 : o4;
            j = r;
        }
        float4 v = ((const float4*)in)[j];
        ((__half2*)out)[2*j]   = __floats2half2_rn(v.x, v.y);
        ((__half2*)out)[2*j+1] = __floats2half2_rn(v.z, v.w);
    }
}

// ---------------------------------------------------------------------------
// Fused attention: one CTA per (b*l, h); outputs fp16
// ---------------------------------------------------------------------------
__global__ void __launch_bounds__(256) attn_kernel(
    const float* __restrict__ img,
    const float* __restrict__ title,
    const int*   __restrict__ mask,
    const float* __restrict__ scale_img,
    const float* __restrict__ scale_title,
    __half*      __restrict__ attn_cat)
{
    const int h   = blockIdx.x & (H_-1);
    const int bl  = blockIdx.x >> 3;
    const int tid = threadIdx.x;

    __shared__ float im[P_][DH_+1];
    __shared__ float ti[T_][DH_+1];
    __shared__ float raw[P_][T_];
    __shared__ float pim[P_][T_];
    __shared__ float pti[T_][P_+3];
    __shared__ float s_si[P_];
    __shared__ float s_st[T_];
    __shared__ int   mk[T_];

    const float* ib = img   + (size_t)bl * (P_*D_) + h*DH_;
    for (int idx = tid; idx < P_*DH_; idx += 256) {
        int p = idx >> 6, d = idx & 63;
        im[p][d] = ib[p*D_ + d];
    }
    const float* tb = title + (size_t)bl * (T_*D_) + h*DH_;
    for (int idx = tid; idx < T_*DH_; idx += 256) {
        int t = idx >> 6, d = idx & 63;
        ti[t][d] = tb[t*D_ + d];
    }
    if (tid < T_) { mk[tid] = mask[bl*T_ + tid]; s_st[tid] = scale_title[h*T_ + tid]; }
    if (tid < P_) s_si[tid] = scale_img[h*P_ + tid];
    __syncthreads();

    for (int idx = tid; idx < P_*T_; idx += 256) {
        int p = idx / T_, t = idx % T_;
        float s = 0.f;
        #pragma unroll 16
        for (int d = 0; d < DH_; d++) s += im[p][d] * ti[t][d];
        raw[p][t] = s * 0.125f;
    }
    __syncthreads();

    if (tid < P_) {
        const int p = tid;
        const float sc = s_si[p];
        float v[T_];
        float mx = -3.4e38f;
        #pragma unroll
        for (int t = 0; t < T_; t++) {
            float x = mk[t] ? raw[p][t]*sc : -1e9f;
            v[t] = x;
            mx = fmaxf(mx, x);
        }
        float s = 0.f;
        #pragma unroll
        for (int t = 0; t < T_; t++) { float e = expf(v[t]-mx); v[t]=e; s+=e; }
        float inv = 1.f/s;
        #pragma unroll
        for (int t = 0; t < T_; t++) pim[p][t] = v[t]*inv;
    }
    if (tid >= 64 && tid < 64+T_) {
        const int t = tid - 64;
        const float sc = s_st[t];
        const bool valid = (mk[t] != 0);
        float mx = -3.4e38f;
        for (int p = 0; p < P_; p++) {
            float x = valid ? raw[p][t]*sc : -1e9f;
            pti[t][p] = x;
            mx = fmaxf(mx, x);
        }
        float s = 0.f;
        for (int p = 0; p < P_; p++) { float e = expf(pti[t][p]-mx); pti[t][p]=e; s+=e; }
        float inv = 1.f/s;
        for (int p = 0; p < P_; p++) pti[t][p] *= inv;
    }
    __syncthreads();

    for (int idx = tid; idx < P_*DH_; idx += 256) {
        int p = idx >> 6, d = idx & 63;
        float s = 0.f;
        #pragma unroll
        for (int t = 0; t < T_; t++) s += pim[p][t]*ti[t][d];
        attn_cat[(size_t)(ROWS_IMG + bl*P_ + p)*D_ + h*DH_ + d] = __float2half_rn(s);
    }
    for (int idx = tid; idx < T_*DH_; idx += 256) {
        int t = idx >> 6, d = idx & 63;
        float s = 0.f;
        #pragma unroll 7
        for (int p = 0; p < P_; p++) s += pti[t][p]*im[p][d];
        attn_cat[(size_t)(bl*T_ + t)*D_ + h*DH_ + d] = __float2half_rn(s);
    }
}

// ---------------------------------------------------------------------------
// fp16 tensor-core GEMM, merged img/tit chains:
// weight/bias selected per CTA by bm < split (split is tile-aligned).
// BM=BN=128, BK=32, 256 thr / 8 warps x (64x32 tile), 3-stage cp.async,
// single barrier per k-tile, mma.sync m16n8k16.
// MODE: 0 = fp32 out C, 1 = fp16 out Ch, 2 = fp32 C + fp16 Ch
// ---------------------------------------------------------------------------
__device__ __forceinline__ float gelu_t(float x) {
    float x3 = x*x*x;
    return 0.5f*x*(1.f + tanhf(0.7978845608028654f*(x + 0.044715f*x3)));
}

__device__ __forceinline__ void mma_h(float* d, const uint32_t* a, const uint32_t* b) {
    asm volatile(
        "mma.sync.aligned.m16n8k16.row.col.f32.f16.f16.f32 "
        "{%0,%1,%2,%3}, {%4,%5,%6,%7}, {%8,%9}, {%0,%1,%2,%3};"
        : "+f"(d[0]), "+f"(d[1]), "+f"(d[2]), "+f"(d[3])
        : "r"(a[0]), "r"(a[1]), "r"(a[2]), "r"(a[3]), "r"(b[0]), "r"(b[1]));
}

__device__ __forceinline__ void cp16(void* smem_dst, const void* gsrc) {
    uint32_t d = (uint32_t)__cvta_generic_to_shared(smem_dst);
    asm volatile("cp.async.cg.shared.global [%0], [%1], 16;" :: "r"(d), "l"(gsrc));
}

__device__ __forceinline__ void ldsm4(uint32_t* r, uint32_t addr) {
    asm volatile("ldmatrix.sync.aligned.m8n8.x4.shared.b16 {%0,%1,%2,%3}, [%4];"
        : "=r"(r[0]), "=r"(r[1]), "=r"(r[2]), "=r"(r[3]) : "r"(addr));
}

#define HPITCH 40          // halves (80 bytes/row)
#define STAGES 3

template<int ACT, int MODE>
__global__ void __launch_bounds__(256, 2) gemm_h(
    const __half* __restrict__ A,
    const __half* __restrict__ W1, const __half* __restrict__ W2,
    const float* __restrict__ bias1, const float* __restrict__ bias2,
    float* __restrict__ C, __half* __restrict__ Ch,
    int M, int N, int K, int split)
{
    __shared__ __half As[STAGES][128][HPITCH];
    __shared__ __half Ws[STAGES][128][HPITCH];

    const int tid  = threadIdx.x;
    const int lane = tid & 31;
    const int warp = tid >> 5;
    const int wm   = warp >> 2;     // 0..1
    const int wn   = warp & 3;      // 0..3

    const int bn = blockIdx.x * 128;
    const int bm = blockIdx.y * 128;

    const bool isA = bm < split;                 // chain select (uniform per CTA)
    const __half* W    = isA ? W1 : W2;
    const float*  bias = isA ? bias1 : bias2;

    const int srow = tid >> 1;
    const int scol = (tid & 1) * 16;
    const int  arow = bm + srow;
    const bool aok  = arow < M;
    const __half* Ap = A + (size_t)arow * K + scol;
    const __half* Wp = W + (size_t)(bn + srow) * K + scol;

    if (!aok) {
        #pragma unroll
        for (int s = 0; s < STAGES; s++)
            #pragma unroll
            for (int j = 0; j < 16; j++)
                As[s][srow][scol + j] = __float2half_rn(0.f);
    }

    float acc[4][4][4];
    #pragma unroll
    for (int mt = 0; mt < 4; mt++)
        #pragma unroll
        for (int nt = 0; nt < 4; nt++)
            #pragma unroll
            for (int r = 0; r < 4; r++) acc[mt][nt][r] = 0.f;

    const int KT = K >> 5;

    #pragma unroll
    for (int s = 0; s < 2; s++) {
        const int ko = s << 5;
        if (aok) { cp16(&As[s][srow][scol], Ap + ko); cp16(&As[s][srow][scol+8], Ap + ko + 8); }
        cp16(&Ws[s][srow][scol], Wp + ko); cp16(&Ws[s][srow][scol+8], Wp + ko + 8);
        asm volatile("cp.async.commit_group;");
    }

    const int a_row  = wm*64 + (lane & 15);
    const int a_colh = ((lane >> 4) & 1) * 8;
    const int b_row  = wn*32 + (lane & 7) + ((lane & 16) >> 1);
    const int b_colh = ((lane >> 3) & 1) * 8;
    uint32_t a_base[STAGES], b_base[STAGES];
    #pragma unroll
    for (int s = 0; s < STAGES; s++) {
        a_base[s] = (uint32_t)__cvta_generic_to_shared(&As[s][a_row][a_colh]);
        b_base[s] = (uint32_t)__cvta_generic_to_shared(&Ws[s][b_row][b_colh]);
    }

    for (int kt = 0; kt < KT; kt++) {
        const int cur = kt % STAGES;
        asm volatile("cp.async.wait_group 1;");
        __syncthreads();
        // Single barrier per iteration (safety argument in round-9 notes).

        if (kt + 2 < KT) {
            const int nb = (kt + 2) % STAGES;
            const int ko = (kt + 2) << 5;
            if (aok) { cp16(&As[nb][srow][scol], Ap + ko); cp16(&As[nb][srow][scol+8], Ap + ko + 8); }
            cp16(&Ws[nb][srow][scol], Wp + ko); cp16(&Ws[nb][srow][scol+8], Wp + ko + 8);
            asm volatile("cp.async.commit_group;");
        }

        #pragma unroll
        for (int kh = 0; kh < 2; kh++) {
            uint32_t af[4][4], bf[2][4];
            #pragma unroll
            for (int mt = 0; mt < 4; mt++)
                ldsm4(af[mt], a_base[cur] + (uint32_t)((kh*16 + mt*16*HPITCH) * 2));
            #pragma unroll
            for (int pr = 0; pr < 2; pr++)
                ldsm4(bf[pr], b_base[cur] + (uint32_t)((kh*16 + pr*16*HPITCH) * 2));
            #pragma unroll
            for (int mt = 0; mt < 4; mt++)
                #pragma unroll
                for (int nt = 0; nt < 4; nt++)
                    mma_h(acc[mt][nt], af[mt], &bf[nt>>1][(nt&1)*2]);
        }
    }

    const int cn = bn + wn*32;
    float bv[4][2];
    #pragma unroll
    for (int nt = 0; nt < 4; nt++) {
        int c = cn + nt*8 + 2*(lane & 3);
        bv[nt][0] = bias[c];
        bv[nt][1] = bias[c+1];
    }
    #pragma unroll
    for (int mt = 0; mt < 4; mt++) {
        const int r0 = bm + wm*64 + mt*16 + (lane >> 2);
        #pragma unroll
        for (int half = 0; half < 2; half++) {
            const int r = r0 + half*8;
            if (r < M) {
                #pragma unroll
                for (int nt = 0; nt < 4; nt++) {
                    float x0 = acc[mt][nt][half*2+0] + bv[nt][0];
                    float x1 = acc[mt][nt][half*2+1] + bv[nt][1];
                    if (ACT) { x0 = gelu_t(x0); x1 = gelu_t(x1); }
                    const size_t off = (size_t)r*N + cn + nt*8 + 2*(lane & 3);
                    if (MODE == 0) {
                        *(float2*)&C[off] = make_float2(x0, x1);
                    } else if (MODE == 1) {
                        *(__half2*)&Ch[off] = __floats2half2_rn(x0, x1);
                    } else {
                        *(float2*)&C[off]   = make_float2(x0, x1);
                        *(__half2*)&Ch[off] = __floats2half2_rn(x0, x1);
                    }
                }
            }
        }
    }
}

// ---------------------------------------------------------------------------
// Merged LN+residual: per-row param select (row < ROWS_IMG -> img params)
// out[row] = hid[row] + a*(x-mean)/(std(ddof=1)+eps) + b
// ---------------------------------------------------------------------------
__global__ void __launch_bounds__(128) ln_res_kernel(
    const float* __restrict__ hid, const float* __restrict__ ffn,
    const float* __restrict__ ga_i, const float* __restrict__ gb_i,
    const float* __restrict__ ga_t, const float* __restrict__ gb_t,
    float* __restrict__ out)
{
    const int row = blockIdx.x;
    const int tid = threadIdx.x;
    const bool isImg = row < ROWS_IMG;
    const float* ga = isImg ? ga_i : ga_t;
    const float* gb = isImg ? gb_i : gb_t;

    float4 xv = ((const float4*)(ffn + (size_t)row*D_))[tid];
    float s = xv.x + xv.y + xv.z + xv.w;
    float q = xv.x*xv.x + xv.y*xv.y + xv.z*xv.z + xv.w*xv.w;
    #pragma unroll
    for (int o = 16; o > 0; o >>= 1) {
        s += __shfl_xor_sync(0xffffffffu, s, o);
        q += __shfl_xor_sync(0xffffffffu, q, o);
    }
    __shared__ float ss[4], sq[4];
    if ((tid & 31) == 0) { ss[tid>>5] = s; sq[tid>>5] = q; }
    __syncthreads();
    float S = ss[0]+ss[1]+ss[2]+ss[3];
    float Q = sq[0]+sq[1]+sq[2]+sq[3];
    float mean = S * (1.f/D_);
    float var  = (Q - (float)D_*mean*mean) * (1.f/(D_-1));
    var = fmaxf(var, 0.f);
    float inv = 1.f / (sqrtf(var) + 1e-6f);

    float4 hv = ((const float4*)(hid + (size_t)row*D_))[tid];
    float4 av = ((const float4*)ga)[tid];
    float4 bv = ((const float4*)gb)[tid];
    float4 o4;
    o4.x = hv.x + av.x*(xv.x-mean)*inv + bv.x;
    o4.y = hv.y + av.y*(xv.y-mean)*inv + bv.y;
    o4.z = hv.z + av.z*(xv.z-mean)*inv + bv.z;
    o4.w = hv.w + av.w*(xv.w-mean)*inv + bv.w;
    ((float4*)(out + (size_t)row*D_))[tid] = o4;
}

// ---------------------------------------------------------------------------
extern "C" void kernel_launch(void* const* d_in, const int* in_sizes, int n_in,
                              void* d_out, int out_size)
{
    const float* img    = (const float*)d_in[0];
    const float* title  = (const float*)d_in[1];
    const int*   mask   = (const int*)  d_in[2];
    const float* s_img  = (const float*)d_in[3];
    const float* s_tit  = (const float*)d_in[4];
    const float* w_proj = (const float*)d_in[5];
    const float* b_proj = (const float*)d_in[6];
    const float* w1i    = (const float*)d_in[7];
    const float* b1i    = (const float*)d_in[8];
    const float* w2i    = (const float*)d_in[9];
    const float* b2i    = (const float*)d_in[10];
    const float* w1t    = (const float*)d_in[11];
    const float* b1t    = (const float*)d_in[12];
    const float* w2t    = (const float*)d_in[13];
    const float* b2t    = (const float*)d_in[14];
    const float* lai    = (const float*)d_in[15];
    const float* lbi    = (const float*)d_in[16];
    const float* lat    = (const float*)d_in[17];
    const float* lbt    = (const float*)d_in[18];
    float* out = (float*)d_out;

    __half *attn, *hidh, *ffh, *wph, *w1ih, *w2ih, *w1th, *w2th;
    float *hid, *ffo;
    cudaGetSymbolAddress((void**)&attn, g_attn);
    cudaGetSymbolAddress((void**)&hid,  g_hid);
    cudaGetSymbolAddress((void**)&hidh, g_hidh);
    cudaGetSymbolAddress((void**)&ffh,  g_ffh);
    cudaGetSymbolAddress((void**)&ffo,  g_ffo);
    cudaGetSymbolAddress((void**)&wph,  g_wph);
    cudaGetSymbolAddress((void**)&w1ih, g_w1ih);
    cudaGetSymbolAddress((void**)&w2ih, g_w2ih);
    cudaGetSymbolAddress((void**)&w1th, g_w1th);
    cudaGetSymbolAddress((void**)&w2th, g_w2th);

    // all 5 weight conversions in one launch
    to_half_all<<<1024, 256>>>(w_proj, w1i, w2i, w1t, w2t,
                               wph, w1ih, w2ih, w1th, w2th);

    attn_kernel<<<B_*L_*H_, 256>>>(img, title, mask, s_img, s_tit, attn);

    // proj over all rows (same weights both chains)
    dim3 gP(D_/128, (ROWS_ALL+127)/128);
    gemm_h<0,2><<<gP, 256>>>(attn, wph, wph, b_proj, b_proj,
                             hid, hidh, ROWS_ALL, D_, D_, ROWS_ALL);

    // FFN1 merged (img rows 0..15999 tile-aligned; tit rows after)
    dim3 g1(DFF_/128, (ROWS_ALL+127)/128);
    gemm_h<1,1><<<g1, 256>>>(hidh, w1ih, w1th, b1i, b1t,
                             (float*)0, ffh, ROWS_ALL, DFF_, D_, ROWS_IMG);

    // FFN2 merged
    dim3 g2(D_/128, (ROWS_ALL+127)/128);
    gemm_h<0,0><<<g2, 256>>>(ffh, w2ih, w2th, b2i, b2t,
                             ffo, (__half*)0, ROWS_ALL, D_, DFF_, ROWS_IMG);

    // LN+residual merged
    ln_res_kernel<<<ROWS_ALL, 128>>>(hid, ffo, lai, lbi, lat, lbt, out);
}